// round 7
// baseline (speedup 1.0000x reference)
#include <cuda_runtime.h>
#include <cuda_bf16.h>
#include <cstdint>

// Problem constants (fixed by the dataset)
#define NV 8192
#define DV 128
#define TILE 128
#define GT (NV / TILE)   // 64 tiles per dim

// -------- device scratch (no allocs allowed) --------
__device__ __nv_bfloat16 g_wbf[(size_t)NV * DV];   // bf16 weights (2 MB, L2-resident)
__device__ float g_sq[NV];                          // fp32 row squared norms
__device__ float g_part[GT * GT];                   // per-tile partial sums

// ============================================================
// Helpers (portable PTX only: compute_103 virtual target — NO tcgen05)
// ============================================================
static __device__ __forceinline__ uint32_t smem_u32(const void* p) {
    uint32_t a;
    asm("{ .reg .u64 t; cvta.to.shared.u64 t, %1; cvt.u32.u64 %0, t; }"
        : "=r"(a) : "l"(p));
    return a;
}
static __device__ __forceinline__ float fsqrt_fast(float x) {
    float r; asm("sqrt.approx.f32 %0, %1;" : "=f"(r) : "f"(x)); return r;
}
static __device__ __forceinline__ void ldsm_x4(uint32_t& r0, uint32_t& r1,
                                               uint32_t& r2, uint32_t& r3,
                                               uint32_t addr) {
    asm volatile("ldmatrix.sync.aligned.m8n8.x4.shared.b16 {%0,%1,%2,%3}, [%4];"
                 : "=r"(r0), "=r"(r1), "=r"(r2), "=r"(r3) : "r"(addr));
}
static __device__ __forceinline__ void ldsm_x2(uint32_t& r0, uint32_t& r1,
                                               uint32_t addr) {
    asm volatile("ldmatrix.sync.aligned.m8n8.x2.shared.b16 {%0,%1}, [%2];"
                 : "=r"(r0), "=r"(r1) : "r"(addr));
}
static __device__ __forceinline__ void mma16816(float* d, const uint32_t* a,
                                                const uint32_t* b) {
    asm volatile(
        "mma.sync.aligned.m16n8k16.row.col.f32.bf16.bf16.f32 "
        "{%0,%1,%2,%3}, {%4,%5,%6,%7}, {%8,%9}, {%0,%1,%2,%3};"
        : "+f"(d[0]), "+f"(d[1]), "+f"(d[2]), "+f"(d[3])
        : "r"(a[0]), "r"(a[1]), "r"(a[2]), "r"(a[3]), "r"(b[0]), "r"(b[1]));
}

// K-staged W tile: 128 rows x 64 bf16 = 128 B/row = 16 KB.
// Row r stored as 8 chunks of 16 B; chunk c placed at c ^ (r & 7)
// -> every ldmatrix 8-thread group hits 8 distinct 16B banks.
static __device__ __forceinline__ uint32_t w_off(int row, int c8) {
    return (uint32_t)(row * 128 + ((c8 ^ (row & 7)) << 4));
}

// ============================================================
// Kernel 1: fp32 weights -> bf16 buffer + squared norms
// ============================================================
__global__ void prep_kernel(const float* __restrict__ w) {
    int t = blockIdx.x * blockDim.x + threadIdx.x;
    int row = t >> 5;
    int lid = t & 31;
    if (row >= NV) return;
    float4 v = reinterpret_cast<const float4*>(w + (size_t)row * DV)[lid];
    __nv_bfloat162 p0 = __float22bfloat162_rn(make_float2(v.x, v.y));
    __nv_bfloat162 p1 = __float22bfloat162_rn(make_float2(v.z, v.w));
    uint2 pk;
    pk.x = *reinterpret_cast<uint32_t*>(&p0);
    pk.y = *reinterpret_cast<uint32_t*>(&p1);
    *reinterpret_cast<uint2*>(&g_wbf[(size_t)row * DV + lid * 4]) = pk;
    float s = v.x * v.x + v.y * v.y + v.z * v.z + v.w * v.w;
    #pragma unroll
    for (int o = 16; o; o >>= 1) s += __shfl_xor_sync(0xffffffffu, s, o);
    if (lid == 0) g_sq[row] = s;
}

// ============================================================
// Kernel 2: one 128x128 Gram tile per CTA via mma.sync (bf16->fp32),
// K=128 in two K=64 SMEM stages (static smem <= 48 KB, no opt-ins).
// 8 warps in 2(m) x 4(n); warp tile 64x32. Fused sqrt + A-weighted reduce.
// ============================================================
__global__ __launch_bounds__(256, 2)
void tile_kernel(const float* __restrict__ A) {
    __shared__ __align__(16) char s_wm[128 * 128];   // 16 KB, current k-stage of Wm
    __shared__ __align__(16) char s_wn[128 * 128];   // 16 KB, current k-stage of Wn
    __shared__ float ssqm[128];
    __shared__ float ssqn[128];
    __shared__ float sred[8];

    const uint32_t sbm = smem_u32(s_wm);
    const uint32_t sbn = smem_u32(s_wn);
    const int tid = threadIdx.x;
    const int wid = tid >> 5;
    const int lid = tid & 31;
    const int wm = wid >> 2;          // 0..1  (m block of 64)
    const int wn = wid & 3;           // 0..3  (n block of 32)
    const int m0 = blockIdx.y * TILE;
    const int n0 = blockIdx.x * TILE;

    // squared norms for this tile's rows / cols
    if (tid < 128) ssqm[tid] = g_sq[m0 + tid];
    else           ssqn[tid - 128] = g_sq[n0 + tid - 128];

    float acc[4][4][4];
    #pragma unroll
    for (int mi = 0; mi < 4; mi++)
        #pragma unroll
        for (int ni = 0; ni < 4; ni++)
            #pragma unroll
            for (int e = 0; e < 4; e++) acc[mi][ni][e] = 0.0f;

    // --- two K=64 stages ---
    #pragma unroll
    for (int kt = 0; kt < 2; kt++) {
        // stage this k-slice of both W tiles (16B vectors, swizzled)
        #pragma unroll
        for (int it = 0; it < 4; it++) {
            int i = tid + it * 256;          // 0..1023
            int row = i >> 3, c8 = i & 7;
            const size_t gk = (size_t)kt * 64 + (c8 << 3);
            uint4 vm = *reinterpret_cast<const uint4*>(
                &g_wbf[(size_t)(m0 + row) * DV + gk]);
            *reinterpret_cast<uint4*>(s_wm + w_off(row, c8)) = vm;
            uint4 vn = *reinterpret_cast<const uint4*>(
                &g_wbf[(size_t)(n0 + row) * DV + gk]);
            *reinterpret_cast<uint4*>(s_wn + w_off(row, c8)) = vn;
        }
        __syncthreads();

        // 4 k16 steps within this stage
        #pragma unroll
        for (int ks = 0; ks < 4; ks++) {
            uint32_t af[4][4], bf[4][2];
            #pragma unroll
            for (int mi = 0; mi < 4; mi++) {
                int row = wm * 64 + mi * 16 + (lid & 15);
                int ch  = ks * 2 + (lid >> 4);
                ldsm_x4(af[mi][0], af[mi][1], af[mi][2], af[mi][3],
                        sbm + w_off(row, ch));
            }
            #pragma unroll
            for (int ni = 0; ni < 4; ni++) {
                int row = wn * 32 + ni * 8 + (lid & 7);
                int ch  = ks * 2 + ((lid >> 3) & 1);
                ldsm_x2(bf[ni][0], bf[ni][1], sbn + w_off(row, ch));
            }
            #pragma unroll
            for (int mi = 0; mi < 4; mi++)
                #pragma unroll
                for (int ni = 0; ni < 4; ni++)
                    mma16816(acc[mi][ni], af[mi], bf[ni]);
        }
        if (kt == 0) __syncthreads();   // protect smem before next stage's stores
    }

    // --- fused epilogue: d2 = sq_m + sq_n - 2*gram; sum A*sqrt(max(d2,0)) ---
    float asum = 0.0f;
    #pragma unroll
    for (int mi = 0; mi < 4; mi++) {
        const int r0 = wm * 64 + mi * 16 + (lid >> 2);   // tile-local row
        const float* Ar0 = A + (size_t)(m0 + r0) * NV + n0;
        const float* Ar8 = Ar0 + (size_t)8 * NV;
        const float sq0 = ssqm[r0];
        const float sq8 = ssqm[r0 + 8];
        // prefetch all 8 float2 for this mi first (raise MLP)
        float2 alo[4], ahi[4];
        #pragma unroll
        for (int ni = 0; ni < 4; ni++) {
            const int c0 = wn * 32 + ni * 8 + 2 * (lid & 3);
            alo[ni] = __ldg(reinterpret_cast<const float2*>(Ar0 + c0));
            ahi[ni] = __ldg(reinterpret_cast<const float2*>(Ar8 + c0));
        }
        #pragma unroll
        for (int ni = 0; ni < 4; ni++) {
            const int c0 = wn * 32 + ni * 8 + 2 * (lid & 3);
            const float sn0 = ssqn[c0], sn1 = ssqn[c0 + 1];
            float d0 = fmaxf(sq0 + sn0 - 2.0f * acc[mi][ni][0], 0.0f);
            float d1 = fmaxf(sq0 + sn1 - 2.0f * acc[mi][ni][1], 0.0f);
            float d2 = fmaxf(sq8 + sn0 - 2.0f * acc[mi][ni][2], 0.0f);
            float d3 = fmaxf(sq8 + sn1 - 2.0f * acc[mi][ni][3], 0.0f);
            asum = fmaf(alo[ni].x, fsqrt_fast(d0), asum);
            asum = fmaf(alo[ni].y, fsqrt_fast(d1), asum);
            asum = fmaf(ahi[ni].x, fsqrt_fast(d2), asum);
            asum = fmaf(ahi[ni].y, fsqrt_fast(d3), asum);
        }
    }

    // --- deterministic reduction: warp -> smem -> thread 0 ---
    #pragma unroll
    for (int o = 16; o; o >>= 1) asum += __shfl_xor_sync(0xffffffffu, asum, o);
    if (lid == 0) sred[wid] = asum;
    __syncthreads();
    if (tid == 0) {
        float s = ((sred[0] + sred[1]) + (sred[2] + sred[3]))
                + ((sred[4] + sred[5]) + (sred[6] + sred[7]));
        g_part[blockIdx.y * GT + blockIdx.x] = s;
    }
}

// ============================================================
// Kernel 3: deterministic final reduction over 4096 partials
// ============================================================
__global__ void reduce_kernel(float* __restrict__ out) {
    __shared__ float sh[256];
    float s = 0.0f;
    for (int i = threadIdx.x; i < GT * GT; i += 256) s += g_part[i];
    sh[threadIdx.x] = s;
    __syncthreads();
    #pragma unroll
    for (int o = 128; o; o >>= 1) {
        if (threadIdx.x < o) sh[threadIdx.x] += sh[threadIdx.x + o];
        __syncthreads();
    }
    if (threadIdx.x == 0) out[0] = sh[0];
}

// ============================================================
// kernel_launch — plain launches only, no attribute calls, no opt-ins
// ============================================================
extern "C" void kernel_launch(void* const* d_in, const int* in_sizes, int n_in,
                              void* d_out, int out_size) {
    const float* A = (const float*)d_in[0];       // [N, N]
    const float* W = (const float*)d_in[1];       // [N, D]
    float* out = (float*)d_out;                   // [1 + N*D]: result then weights

    // weights pass-through (exact copy), overlaps with compute
    if (out_size >= 1 + NV * DV) {
        cudaMemcpyAsync(out + 1, W, (size_t)NV * DV * sizeof(float),
                        cudaMemcpyDeviceToDevice, 0);
    }

    prep_kernel<<<(NV * 32) / 256, 256>>>(W);

    dim3 grid(GT, GT);
    tile_kernel<<<grid, 256>>>(A);

    reduce_kernel<<<1, 256>>>(out);
}

// round 11
// speedup vs baseline: 1.0965x; 1.0965x over previous
#include <cuda_runtime.h>
#include <cuda_bf16.h>
#include <cstdint>

// Problem constants (fixed by the dataset)
#define NV 8192
#define DV 128
#define TILE 128
#define GT (NV / TILE)   // 64 tiles per dim

// -------- device scratch (no allocs allowed) --------
__device__ __nv_bfloat16 g_wbf[(size_t)NV * DV];   // bf16 weights (2 MB, L2-resident)
__device__ float g_sq[NV];                          // fp32 row squared norms
__device__ float g_part[GT * GT];                   // per-tile partial sums

// ============================================================
// Helpers (portable PTX only: compute_103 virtual target — NO tcgen05)
// ============================================================
static __device__ __forceinline__ uint32_t smem_u32(const void* p) {
    uint32_t a;
    asm("{ .reg .u64 t; cvta.to.shared.u64 t, %1; cvt.u32.u64 %0, t; }"
        : "=r"(a) : "l"(p));
    return a;
}
static __device__ __forceinline__ float fsqrt_fast(float x) {
    float r; asm("sqrt.approx.f32 %0, %1;" : "=f"(r) : "f"(x)); return r;
}
static __device__ __forceinline__ void ldsm_x4(uint32_t& r0, uint32_t& r1,
                                               uint32_t& r2, uint32_t& r3,
                                               uint32_t addr) {
    asm volatile("ldmatrix.sync.aligned.m8n8.x4.shared.b16 {%0,%1,%2,%3}, [%4];"
                 : "=r"(r0), "=r"(r1), "=r"(r2), "=r"(r3) : "r"(addr));
}
static __device__ __forceinline__ void ldsm_x2(uint32_t& r0, uint32_t& r1,
                                               uint32_t addr) {
    asm volatile("ldmatrix.sync.aligned.m8n8.x2.shared.b16 {%0,%1}, [%2];"
                 : "=r"(r0), "=r"(r1) : "r"(addr));
}
static __device__ __forceinline__ void mma16816(float* d, const uint32_t* a,
                                                const uint32_t* b) {
    asm volatile(
        "mma.sync.aligned.m16n8k16.row.col.f32.bf16.bf16.f32 "
        "{%0,%1,%2,%3}, {%4,%5,%6,%7}, {%8,%9}, {%0,%1,%2,%3};"
        : "+f"(d[0]), "+f"(d[1]), "+f"(d[2]), "+f"(d[3])
        : "r"(a[0]), "r"(a[1]), "r"(a[2]), "r"(a[3]), "r"(b[0]), "r"(b[1]));
}

// K-staged W tile: 128 rows x 64 bf16 = 128 B/row = 16 KB.
// Row r stored as 8 chunks of 16 B; chunk c placed at c ^ (r & 7)
// -> every ldmatrix 8-thread group hits 8 distinct 16B banks.
static __device__ __forceinline__ uint32_t w_off(int row, int c8) {
    return (uint32_t)(row * 128 + ((c8 ^ (row & 7)) << 4));
}

// ============================================================
// Kernel 1: fp32 weights -> bf16 buffer + squared norms
// ============================================================
__global__ void prep_kernel(const float* __restrict__ w) {
    int t = blockIdx.x * blockDim.x + threadIdx.x;
    int row = t >> 5;
    int lid = t & 31;
    if (row >= NV) return;
    float4 v = reinterpret_cast<const float4*>(w + (size_t)row * DV)[lid];
    __nv_bfloat162 p0 = __float22bfloat162_rn(make_float2(v.x, v.y));
    __nv_bfloat162 p1 = __float22bfloat162_rn(make_float2(v.z, v.w));
    uint2 pk;
    pk.x = *reinterpret_cast<uint32_t*>(&p0);
    pk.y = *reinterpret_cast<uint32_t*>(&p1);
    *reinterpret_cast<uint2*>(&g_wbf[(size_t)row * DV + lid * 4]) = pk;
    float s = v.x * v.x + v.y * v.y + v.z * v.z + v.w * v.w;
    #pragma unroll
    for (int o = 16; o; o >>= 1) s += __shfl_xor_sync(0xffffffffu, s, o);
    if (lid == 0) g_sq[row] = s;
}

// ============================================================
// Kernel 2: SYMMETRIC tiles — only ti<=tj computed.
// Off-diagonal tiles use weight (A[i,j] + A[j,i]) on one dist evaluation,
// halving MMA + sqrt work. A DRAM traffic unchanged (tile + transpose read).
// 8 warps in 2(m) x 4(n); warp tile 64x32; K=128 in two K=64 SMEM stages.
// ============================================================
__global__ __launch_bounds__(256, 2)
void tile_kernel(const float* __restrict__ A) {
    const int tj = blockIdx.x;       // n tile
    const int ti = blockIdx.y;       // m tile
    if (ti > tj) return;             // lower triangle handled by symmetry
    const bool diag = (ti == tj);

    __shared__ __align__(16) char s_wm[128 * 128];   // 16 KB, current k-stage of Wm
    __shared__ __align__(16) char s_wn[128 * 128];   // 16 KB, current k-stage of Wn
    __shared__ float ssqm[128];
    __shared__ float ssqn[128];
    __shared__ float sred[8];

    const uint32_t sbm = smem_u32(s_wm);
    const uint32_t sbn = smem_u32(s_wn);
    const int tid = threadIdx.x;
    const int wid = tid >> 5;
    const int lid = tid & 31;
    const int wm = wid >> 2;          // 0..1  (m block of 64)
    const int wn = wid & 3;           // 0..3  (n block of 32)
    const int m0 = ti * TILE;
    const int n0 = tj * TILE;

    // squared norms for this tile's rows / cols
    if (tid < 128) ssqm[tid] = g_sq[m0 + tid];
    else           ssqn[tid - 128] = g_sq[n0 + tid - 128];

    float acc[4][4][4];
    #pragma unroll
    for (int mi = 0; mi < 4; mi++)
        #pragma unroll
        for (int ni = 0; ni < 4; ni++)
            #pragma unroll
            for (int e = 0; e < 4; e++) acc[mi][ni][e] = 0.0f;

    // --- two K=64 stages ---
    #pragma unroll
    for (int kt = 0; kt < 2; kt++) {
        // stage this k-slice of both W tiles (16B vectors, swizzled)
        #pragma unroll
        for (int it = 0; it < 4; it++) {
            int i = tid + it * 256;          // 0..1023
            int row = i >> 3, c8 = i & 7;
            const size_t gk = (size_t)kt * 64 + (c8 << 3);
            uint4 vm = *reinterpret_cast<const uint4*>(
                &g_wbf[(size_t)(m0 + row) * DV + gk]);
            *reinterpret_cast<uint4*>(s_wm + w_off(row, c8)) = vm;
            uint4 vn = *reinterpret_cast<const uint4*>(
                &g_wbf[(size_t)(n0 + row) * DV + gk]);
            *reinterpret_cast<uint4*>(s_wn + w_off(row, c8)) = vn;
        }
        __syncthreads();

        // 4 k16 steps within this stage
        #pragma unroll
        for (int ks = 0; ks < 4; ks++) {
            uint32_t af[4][4], bf[4][2];
            #pragma unroll
            for (int mi = 0; mi < 4; mi++) {
                int row = wm * 64 + mi * 16 + (lid & 15);
                int ch  = ks * 2 + (lid >> 4);
                ldsm_x4(af[mi][0], af[mi][1], af[mi][2], af[mi][3],
                        sbm + w_off(row, ch));
            }
            #pragma unroll
            for (int ni = 0; ni < 4; ni++) {
                int row = wn * 32 + ni * 8 + (lid & 7);
                int ch  = ks * 2 + ((lid >> 3) & 1);
                ldsm_x2(bf[ni][0], bf[ni][1], sbn + w_off(row, ch));
            }
            #pragma unroll
            for (int mi = 0; mi < 4; mi++)
                #pragma unroll
                for (int ni = 0; ni < 4; ni++)
                    mma16816(acc[mi][ni], af[mi], bf[ni]);
        }
        if (kt == 0) __syncthreads();   // protect smem before next stage's stores
    }

    // --- fused epilogue ---
    // off-diag: weight = A[m0+r][n0+c] + A[n0+c][m0+r]; diag: weight = A only.
    float asum0 = 0.0f, asum1 = 0.0f;
    #pragma unroll
    for (int mi = 0; mi < 4; mi++) {
        const int rb = wm * 64 + mi * 16 + (lid >> 2);   // tile-local row
        const float* Ar0 = A + (size_t)(m0 + rb) * NV + n0;
        const float* Ar8 = Ar0 + (size_t)8 * NV;
        const float sq0 = ssqm[rb];
        const float sq8 = ssqm[rb + 8];
        // prefetch all direct-tile A (8 float2) first to raise MLP
        float2 alo[4], ahi[4];
        #pragma unroll
        for (int ni = 0; ni < 4; ni++) {
            const int c0 = wn * 32 + ni * 8 + 2 * (lid & 3);
            alo[ni] = __ldg(reinterpret_cast<const float2*>(Ar0 + c0));
            ahi[ni] = __ldg(reinterpret_cast<const float2*>(Ar8 + c0));
        }
        // transposed-tile A (uniform branch per CTA); 8 lanes with the same c
        // read 8 consecutive floats -> full 32B sectors
        float a2[4][4];
        if (!diag) {
            #pragma unroll
            for (int ni = 0; ni < 4; ni++) {
                const int c0 = wn * 32 + ni * 8 + 2 * (lid & 3);
                const float* At = A + (size_t)(n0 + c0) * NV + (m0 + rb);
                a2[ni][0] = __ldg(At);            // A[n0+c0  ][m0+rb  ]
                a2[ni][1] = __ldg(At + NV);       // A[n0+c0+1][m0+rb  ]
                a2[ni][2] = __ldg(At + 8);        // A[n0+c0  ][m0+rb+8]
                a2[ni][3] = __ldg(At + NV + 8);   // A[n0+c0+1][m0+rb+8]
            }
        } else {
            #pragma unroll
            for (int ni = 0; ni < 4; ni++)
                #pragma unroll
                for (int e = 0; e < 4; e++) a2[ni][e] = 0.0f;
        }
        #pragma unroll
        for (int ni = 0; ni < 4; ni++) {
            const int c0 = wn * 32 + ni * 8 + 2 * (lid & 3);
            const float sn0 = ssqn[c0], sn1 = ssqn[c0 + 1];
            float d0 = fmaxf(sq0 + sn0 - 2.0f * acc[mi][ni][0], 0.0f);
            float d1 = fmaxf(sq0 + sn1 - 2.0f * acc[mi][ni][1], 0.0f);
            float d2 = fmaxf(sq8 + sn0 - 2.0f * acc[mi][ni][2], 0.0f);
            float d3 = fmaxf(sq8 + sn1 - 2.0f * acc[mi][ni][3], 0.0f);
            asum0 = fmaf(alo[ni].x + a2[ni][0], fsqrt_fast(d0), asum0);
            asum1 = fmaf(alo[ni].y + a2[ni][1], fsqrt_fast(d1), asum1);
            asum0 = fmaf(ahi[ni].x + a2[ni][2], fsqrt_fast(d2), asum0);
            asum1 = fmaf(ahi[ni].y + a2[ni][3], fsqrt_fast(d3), asum1);
        }
    }
    float asum = asum0 + asum1;

    // --- deterministic reduction: warp -> smem -> thread 0 ---
    #pragma unroll
    for (int o = 16; o; o >>= 1) asum += __shfl_xor_sync(0xffffffffu, asum, o);
    if (lid == 0) sred[wid] = asum;
    __syncthreads();
    if (tid == 0) {
        float s = ((sred[0] + sred[1]) + (sred[2] + sred[3]))
                + ((sred[4] + sred[5]) + (sred[6] + sred[7]));
        g_part[ti * GT + tj] = s;
    }
}

// ============================================================
// Kernel 3: deterministic final reduction (upper-triangle partials only)
// ============================================================
__global__ void reduce_kernel(float* __restrict__ out) {
    __shared__ float sh[256];
    float s = 0.0f;
    for (int i = threadIdx.x; i < GT * GT; i += 256) {
        int ti = i / GT, tj = i % GT;
        if (ti <= tj) s += g_part[i];
    }
    sh[threadIdx.x] = s;
    __syncthreads();
    #pragma unroll
    for (int o = 128; o; o >>= 1) {
        if (threadIdx.x < o) sh[threadIdx.x] += sh[threadIdx.x + o];
        __syncthreads();
    }
    if (threadIdx.x == 0) out[0] = sh[0];
}

// ============================================================
// kernel_launch — plain launches only, no attribute calls, no opt-ins
// ============================================================
extern "C" void kernel_launch(void* const* d_in, const int* in_sizes, int n_in,
                              void* d_out, int out_size) {
    const float* A = (const float*)d_in[0];       // [N, N]
    const float* W = (const float*)d_in[1];       // [N, D]
    float* out = (float*)d_out;                   // [1 + N*D]: result then weights

    // weights pass-through (exact copy), overlaps with compute
    if (out_size >= 1 + NV * DV) {
        cudaMemcpyAsync(out + 1, W, (size_t)NV * DV * sizeof(float),
                        cudaMemcpyDeviceToDevice, 0);
    }

    prep_kernel<<<(NV * 32) / 256, 256>>>(W);

    dim3 grid(GT, GT);
    tile_kernel<<<grid, 256>>>(A);

    reduce_kernel<<<1, 256>>>(out);
}